// round 5
// baseline (speedup 1.0000x reference)
#include <cuda_runtime.h>
#include <cuda_bf16.h>
#include <cuda_fp16.h>
#include <cstdint>

#define NMAX 100000
#define HD 128

// Scratch (allocation-free rule)
__device__ float g_z [NMAX * HD];   // used as __half (Z fp16)
__device__ float g_zi[NMAX * HD];   // used as __half (Zi fp16)
__device__ float g_ss[NMAX];
__device__ float g_sd[NMAX];
__device__ float g_h1[NMAX * HD];

// ======================= helpers =======================
__device__ __forceinline__ uint32_t smem_u32(const void* p) {
    uint32_t a;
    asm("{ .reg .u64 t; cvta.to.shared.u64 t, %1; cvt.u32.u64 %0, t; }" : "=r"(a) : "l"(p));
    return a;
}
__device__ __forceinline__ void ldsm4(uint32_t* r, uint32_t addr) {
    asm volatile("ldmatrix.sync.aligned.m8n8.x4.shared.b16 {%0,%1,%2,%3}, [%4];"
                 : "=r"(r[0]), "=r"(r[1]), "=r"(r[2]), "=r"(r[3]) : "r"(addr));
}
__device__ __forceinline__ void mma16816(float* d, const uint32_t* a, const uint32_t* b) {
    asm volatile(
        "mma.sync.aligned.m16n8k16.row.col.f32.bf16.bf16.f32 "
        "{%0,%1,%2,%3}, {%4,%5,%6,%7}, {%8,%9}, {%0,%1,%2,%3};"
        : "+f"(d[0]), "+f"(d[1]), "+f"(d[2]), "+f"(d[3])
        : "r"(a[0]), "r"(a[1]), "r"(a[2]), "r"(a[3]), "r"(b[0]), "r"(b[1]));
}
__device__ __forceinline__ uint32_t packbf2(float x, float y) {
    __nv_bfloat162 h;
    h.x = __float2bfloat16_rn(x); h.y = __float2bfloat16_rn(y);
    return *(uint32_t*)&h;
}
__device__ __forceinline__ void split8(const float4& v0, const float4& v1, uint4& hi, uint4& lo) {
    hi.x = packbf2(v0.x, v0.y); hi.y = packbf2(v0.z, v0.w);
    hi.z = packbf2(v1.x, v1.y); hi.w = packbf2(v1.z, v1.w);
    __nv_bfloat162* hp = (__nv_bfloat162*)&hi;
    lo.x = packbf2(v0.x - __bfloat162float(hp[0].x), v0.y - __bfloat162float(hp[0].y));
    lo.y = packbf2(v0.z - __bfloat162float(hp[1].x), v0.w - __bfloat162float(hp[1].y));
    lo.z = packbf2(v1.x - __bfloat162float(hp[2].x), v1.y - __bfloat162float(hp[2].y));
    lo.w = packbf2(v1.z - __bfloat162float(hp[3].x), v1.w - __bfloat162float(hp[3].y));
}

// SMEM byte offsets
#define OF_WA   0
#define OF_RED  1024
#define OF_AHI  4096       // 128x128 bf16 = 32768
#define OF_ALO  36864
#define OF_BHI  69632      // 256x128 bf16 = 65536
#define OF_BLO  135168
#define SMEM_SZ 200704

// ============ persistent split-bf16 mma.sync GEMM (pipelined) ============
__global__ __launch_bounds__(512, 1)
void gemm_mma(const float* __restrict__ A, const float* __restrict__ Ww,
              const float* __restrict__ Wu, const float* __restrict__ Wa,
              __half* __restrict__ Zh, __half* __restrict__ Zih,
              float* __restrict__ Ssrc, float* __restrict__ Sdst,
              int n, int ntiles)
{
    extern __shared__ char sm[];
    const uint32_t smb = smem_u32(sm);
    const int tid = threadIdx.x, warp = tid >> 5, lane = tid & 31;
    const int wr = warp >> 2, wc = warp & 3;
    const int r0 = wr * 32, n0 = wc * 64;

    if (tid < 256) ((float*)(sm + OF_WA))[tid] = Wa[tid];

    // ---- convert B once per CTA ----
    for (int i = tid; i < 4096; i += 512) {
        int r = i >> 4, ch = i & 15;
        const float* W = (r < 128) ? Ww : Wu;
        const float* g = W + (size_t)(r & 127) * HD + ch * 8;
        float4 v0 = *(const float4*)g, v1 = *(const float4*)(g + 4);
        uint4 hi, lo; split8(v0, v1, hi, lo);
        uint32_t off = (uint32_t)r * 256u + (uint32_t)(ch ^ (r & 7)) * 16u;
        *(uint4*)(sm + OF_BHI + off) = hi;
        *(uint4*)(sm + OF_BLO + off) = lo;
    }

    // ldmatrix lane mappings (precompute row-dependent parts)
    const int akb = lane >> 4;
    const int bkb = (lane >> 3) & 1;
    uint32_t aoff[2]; int amsk[2];
    #pragma unroll
    for (int mi = 0; mi < 2; mi++) {
        int r = r0 + mi * 16 + (lane & 15);
        aoff[mi] = (uint32_t)r * 256u; amsk[mi] = r & 7;
    }
    uint32_t boff[4]; int bmsk[4];
    #pragma unroll
    for (int p = 0; p < 4; p++) {
        int r = n0 + p * 16 + ((lane >> 4) << 3) + (lane & 7);
        boff[p] = (uint32_t)r * 256u; bmsk[p] = r & 7;
    }

    // per-thread A chunk mapping
    int crow[4], cch[4];
    #pragma unroll
    for (int i = 0; i < 4; i++) { int idx = tid + i * 512; crow[i] = idx >> 4; cch[i] = idx & 15; }

    // prefetch first tile's A
    float4 va[4][2];
    {
        int p0 = blockIdx.x * 128;
        #pragma unroll
        for (int i = 0; i < 4; i++) {
            bool p = (blockIdx.x < ntiles) && (p0 + crow[i] < n);
            const float* g = A + (size_t)(p0 + crow[i]) * HD + cch[i] * 8;
            va[i][0] = p ? *(const float4*)g       : make_float4(0.f,0.f,0.f,0.f);
            va[i][1] = p ? *(const float4*)(g + 4) : make_float4(0.f,0.f,0.f,0.f);
        }
    }
    __syncthreads();

    float* red = (float*)(sm + OF_RED);
    const float* WaS = (const float*)(sm + OF_WA);

    for (int tile = blockIdx.x; tile < ntiles; tile += gridDim.x) {
        const int row0 = tile * 128;
        const bool full = (row0 + 128 <= n);

        // ---- convert prefetched A -> smem hi/lo ----
        #pragma unroll
        for (int i = 0; i < 4; i++) {
            uint4 hi, lo; split8(va[i][0], va[i][1], hi, lo);
            uint32_t off = (uint32_t)crow[i] * 256u + (uint32_t)(cch[i] ^ (crow[i] & 7)) * 16u;
            *(uint4*)(sm + OF_AHI + off) = hi;
            *(uint4*)(sm + OF_ALO + off) = lo;
        }
        __syncthreads();

        // ---- pipelined MMA: 24 flattened steps (3 passes x 8 k-steps) ----
        float c[2][8][4];
        #pragma unroll
        for (int mi = 0; mi < 2; mi++)
            #pragma unroll
            for (int nt = 0; nt < 8; nt++)
                #pragma unroll
                for (int q = 0; q < 4; q++) c[mi][nt][q] = 0.f;

        const uint32_t ab0 = smb + OF_AHI, ab2 = smb + OF_ALO;
        const uint32_t bb0 = smb + OF_BHI, bb1 = smb + OF_BLO;

        uint32_t a[2][2][4], b[2][4][4];
        // prologue: load step 0
        #pragma unroll
        for (int mi = 0; mi < 2; mi++)
            ldsm4(a[0][mi], ab0 + aoff[mi] + (uint32_t)((akb) ^ amsk[mi]) * 16u);
        #pragma unroll
        for (int p = 0; p < 4; p++)
            ldsm4(b[0][p], bb0 + boff[p] + (uint32_t)((bkb) ^ bmsk[p]) * 16u);

        #pragma unroll
        for (int t = 0; t < 24; t++) {
            const int cur = t & 1, nxt = cur ^ 1;
            if (t < 23) {
                const int tn = t + 1;
                const int pn = tn >> 3, sn = tn & 7;
                const uint32_t ab = (pn == 2) ? ab2 : ab0;
                const uint32_t bb = (pn == 1) ? bb1 : bb0;
                #pragma unroll
                for (int mi = 0; mi < 2; mi++)
                    ldsm4(a[nxt][mi], ab + aoff[mi] + (uint32_t)((2 * sn + akb) ^ amsk[mi]) * 16u);
                #pragma unroll
                for (int p = 0; p < 4; p++)
                    ldsm4(b[nxt][p], bb + boff[p] + (uint32_t)((2 * sn + bkb) ^ bmsk[p]) * 16u);
            }
            #pragma unroll
            for (int mi = 0; mi < 2; mi++)
                #pragma unroll
                for (int p = 0; p < 4; p++) {
                    mma16816(c[mi][2 * p],     a[cur][mi], &b[cur][p][0]);
                    mma16816(c[mi][2 * p + 1], a[cur][mi], &b[cur][p][2]);
                }
        }

        // ---- prefetch next tile's A ----
        {
            int pt = tile + gridDim.x;
            int p0 = pt * 128;
            #pragma unroll
            for (int i = 0; i < 4; i++) {
                bool p = (pt < ntiles) && (p0 + crow[i] < n);
                const float* g = A + (size_t)(p0 + crow[i]) * HD + cch[i] * 8;
                va[i][0] = p ? *(const float4*)g       : make_float4(0.f,0.f,0.f,0.f);
                va[i][1] = p ? *(const float4*)(g + 4) : make_float4(0.f,0.f,0.f,0.f);
            }
        }

        // ---- epilogue ----
        if (wc < 2) {   // Z columns: row-dots + fp16 stores
            float ssv[2][2] = {{0.f,0.f},{0.f,0.f}}, sdv[2][2] = {{0.f,0.f},{0.f,0.f}};
            #pragma unroll
            for (int mi = 0; mi < 2; mi++)
                #pragma unroll
                for (int nt = 0; nt < 8; nt++) {
                    int col = n0 + nt * 8 + (lane & 3) * 2;
                    float s0 = WaS[col], s1 = WaS[col + 1];
                    float d0 = WaS[128 + col], d1 = WaS[128 + col + 1];
                    ssv[mi][0] += c[mi][nt][0] * s0 + c[mi][nt][1] * s1;
                    ssv[mi][1] += c[mi][nt][2] * s0 + c[mi][nt][3] * s1;
                    sdv[mi][0] += c[mi][nt][0] * d0 + c[mi][nt][1] * d1;
                    sdv[mi][1] += c[mi][nt][2] * d0 + c[mi][nt][3] * d1;
                    int rA = row0 + r0 + mi * 16 + (lane >> 2), rB = rA + 8;
                    __half2 hA = __floats2half2_rn(c[mi][nt][0], c[mi][nt][1]);
                    __half2 hB = __floats2half2_rn(c[mi][nt][2], c[mi][nt][3]);
                    if (full || rA < n) *(__half2*)(Zh + (size_t)rA * HD + col) = hA;
                    if (full || rB < n) *(__half2*)(Zh + (size_t)rB * HD + col) = hB;
                }
            #pragma unroll
            for (int mi = 0; mi < 2; mi++)
                #pragma unroll
                for (int h = 0; h < 2; h++) {
                    ssv[mi][h] += __shfl_xor_sync(0xffffffffu, ssv[mi][h], 1);
                    ssv[mi][h] += __shfl_xor_sync(0xffffffffu, ssv[mi][h], 2);
                    sdv[mi][h] += __shfl_xor_sync(0xffffffffu, sdv[mi][h], 1);
                    sdv[mi][h] += __shfl_xor_sync(0xffffffffu, sdv[mi][h], 2);
                }
            if ((lane & 3) == 0) {
                int g = lane >> 2;
                #pragma unroll
                for (int mi = 0; mi < 2; mi++) {
                    int rl = r0 + mi * 16 + g;
                    red[rl * 2 + wc]             = ssv[mi][0];
                    red[(rl + 8) * 2 + wc]       = ssv[mi][1];
                    red[256 + rl * 2 + wc]       = sdv[mi][0];
                    red[256 + (rl + 8) * 2 + wc] = sdv[mi][1];
                }
            }
        } else {        // Zi columns: fp16 stores
            #pragma unroll
            for (int mi = 0; mi < 2; mi++)
                #pragma unroll
                for (int nt = 0; nt < 8; nt++) {
                    int col = n0 - 128 + nt * 8 + (lane & 3) * 2;
                    int rA = row0 + r0 + mi * 16 + (lane >> 2), rB = rA + 8;
                    __half2 hA = __floats2half2_rn(c[mi][nt][0], c[mi][nt][1]);
                    __half2 hB = __floats2half2_rn(c[mi][nt][2], c[mi][nt][3]);
                    if (full || rA < n) *(__half2*)(Zih + (size_t)rA * HD + col) = hA;
                    if (full || rB < n) *(__half2*)(Zih + (size_t)rB * HD + col) = hB;
                }
        }
        __syncthreads();
        if (tid < 128) {
            int grow = row0 + tid;
            if (grow < n) {
                Ssrc[grow] = red[tid * 2] + red[tid * 2 + 1];
                Sdst[grow] = red[256 + tid * 2] + red[256 + tid * 2 + 1];
            }
        }
    }
}

// ================== edge / attention kernel (Z, Zi in fp16) =====================
__global__ __launch_bounds__(256)
void edge_kernel(const __half* __restrict__ Zh, const __half* __restrict__ Zih,
                 const float* __restrict__ Ssrc, const float* __restrict__ Sdst,
                 const float* __restrict__ edge_d, const int* __restrict__ esrc,
                 const float* __restrict__ W_V, const float* __restrict__ Wa,
                 float* __restrict__ out, int n)
{
    int gw = (blockIdx.x * blockDim.x + threadIdx.x) >> 5;
    if (gw >= n) return;
    const int lane = threadIdx.x & 31;
    const int node = gw;
    const float cva = W_V[0] * Wa[2 * HD];

    int   e   = node * 16 + (lane & 15);
    int   src = esrc[e];
    float ee  = Ssrc[src] + Sdst[node] + edge_d[e] * cva;
    ee = ee > 0.f ? ee : 0.01f * ee;

    float m = ee;
    #pragma unroll
    for (int off = 8; off; off >>= 1) m = fmaxf(m, __shfl_xor_sync(0xffffffffu, m, off));
    float ex = __expf(ee - m);
    float s = ex;
    #pragma unroll
    for (int off = 8; off; off >>= 1) s += __shfl_xor_sync(0xffffffffu, s, off);
    float alpha = ex / s;

    float4 acc = make_float4(0.f, 0.f, 0.f, 0.f);
    #pragma unroll
    for (int j = 0; j < 16; j++) {
        float aj = __shfl_sync(0xffffffffu, alpha, j);
        int   sj = __shfl_sync(0xffffffffu, src,   j);
        uint2 raw = *(const uint2*)(Zh + (size_t)sj * HD + lane * 4);
        float2 f0 = __half22float2(*(__half2*)&raw.x);
        float2 f1 = __half22float2(*(__half2*)&raw.y);
        acc.x += aj * f0.x; acc.y += aj * f0.y; acc.z += aj * f1.x; acc.w += aj * f1.y;
    }

    uint2 zr = *(const uint2*)(Zih + (size_t)node * HD + lane * 4);
    float2 z0 = __half22float2(*(__half2*)&zr.x);
    float2 z1 = __half22float2(*(__half2*)&zr.y);
    float4 o;
    o.x = fmaxf(z0.x + acc.x, 0.f);
    o.y = fmaxf(z0.y + acc.y, 0.f);
    o.z = fmaxf(z1.x + acc.z, 0.f);
    o.w = fmaxf(z1.y + acc.w, 0.f);
    *(float4*)(out + (size_t)node * HD + lane * 4) = o;
}

extern "C" void kernel_launch(void* const* d_in, const int* in_sizes, int n_in,
                              void* d_out, int out_size)
{
    const float* attr   = (const float*)d_in[0];
    const float* edge_d = (const float*)d_in[1];
    const float* W_V1   = (const float*)d_in[2];
    const float* W_W1   = (const float*)d_in[3];
    const float* W_U1   = (const float*)d_in[4];
    const float* W_a1   = (const float*)d_in[5];
    const float* W_V2   = (const float*)d_in[6];
    const float* W_W2   = (const float*)d_in[7];
    const float* W_U2   = (const float*)d_in[8];
    const float* W_a2   = (const float*)d_in[9];
    const int*   esrc   = (const int*)d_in[10];

    const int n = in_sizes[0] / HD;

    float *zp, *zip, *ssp, *sdp, *h1p;
    cudaGetSymbolAddress((void**)&zp,  g_z);
    cudaGetSymbolAddress((void**)&zip, g_zi);
    cudaGetSymbolAddress((void**)&ssp, g_ss);
    cudaGetSymbolAddress((void**)&sdp, g_sd);
    cudaGetSymbolAddress((void**)&h1p, g_h1);
    __half* zhp  = (__half*)zp;
    __half* zihp = (__half*)zip;

    cudaFuncSetAttribute(gemm_mma, cudaFuncAttributeMaxDynamicSharedMemorySize, SMEM_SZ);

    int nsm = 148;
    cudaDeviceGetAttribute(&nsm, cudaDevAttrMultiProcessorCount, 0);

    const int ntiles = (n + 127) / 128;
    const int gb = (nsm < ntiles) ? nsm : ntiles;
    const int eb = (n + 7) / 8;

    gemm_mma<<<gb, 512, SMEM_SZ>>>(attr, W_W1, W_U1, W_a1, zhp, zihp, ssp, sdp, n, ntiles);
    edge_kernel<<<eb, 256>>>(zhp, zihp, ssp, sdp, edge_d, esrc, W_V1, W_a1, h1p, n);
    gemm_mma<<<gb, 512, SMEM_SZ>>>(h1p, W_W2, W_U2, W_a2, zhp, zihp, ssp, sdp, n, ntiles);
    edge_kernel<<<eb, 256>>>(zhp, zihp, ssp, sdp, edge_d, esrc, W_V2, W_a2, (float*)d_out, n);
}

// round 7
// speedup vs baseline: 1.6169x; 1.6169x over previous
#include <cuda_runtime.h>
#include <cuda_bf16.h>
#include <cuda_fp16.h>
#include <cstdint>

#define NMAX 100000
#define HD 128

// Scratch (allocation-free rule)
__device__ float g_z [NMAX * HD];   // used as __half (Z fp16)
__device__ float g_zi[NMAX * HD];   // used as __half (Zi fp16)
__device__ float g_ss[NMAX];
__device__ float g_sd[NMAX];
__device__ float g_h1[NMAX * HD];

// ======================= helpers =======================
__device__ __forceinline__ uint32_t smem_u32(const void* p) {
    uint32_t a;
    asm("{ .reg .u64 t; cvta.to.shared.u64 t, %1; cvt.u32.u64 %0, t; }" : "=r"(a) : "l"(p));
    return a;
}
__device__ __forceinline__ void ldsm4(uint32_t* r, uint32_t addr) {
    asm volatile("ldmatrix.sync.aligned.m8n8.x4.shared.b16 {%0,%1,%2,%3}, [%4];"
                 : "=r"(r[0]), "=r"(r[1]), "=r"(r[2]), "=r"(r[3]) : "r"(addr));
}
__device__ __forceinline__ void mma16816(float* d, const uint32_t* a, const uint32_t* b) {
    asm volatile(
        "mma.sync.aligned.m16n8k16.row.col.f32.bf16.bf16.f32 "
        "{%0,%1,%2,%3}, {%4,%5,%6,%7}, {%8,%9}, {%0,%1,%2,%3};"
        : "+f"(d[0]), "+f"(d[1]), "+f"(d[2]), "+f"(d[3])
        : "r"(a[0]), "r"(a[1]), "r"(a[2]), "r"(a[3]), "r"(b[0]), "r"(b[1]));
}
__device__ __forceinline__ uint32_t packbf2(float x, float y) {
    __nv_bfloat162 h;
    h.x = __float2bfloat16_rn(x); h.y = __float2bfloat16_rn(y);
    return *(uint32_t*)&h;
}
__device__ __forceinline__ void split8(const float4& v0, const float4& v1, uint4& hi, uint4& lo) {
    hi.x = packbf2(v0.x, v0.y); hi.y = packbf2(v0.z, v0.w);
    hi.z = packbf2(v1.x, v1.y); hi.w = packbf2(v1.z, v1.w);
    __nv_bfloat162* hp = (__nv_bfloat162*)&hi;
    lo.x = packbf2(v0.x - __bfloat162float(hp[0].x), v0.y - __bfloat162float(hp[0].y));
    lo.y = packbf2(v0.z - __bfloat162float(hp[1].x), v0.w - __bfloat162float(hp[1].y));
    lo.z = packbf2(v1.x - __bfloat162float(hp[2].x), v1.y - __bfloat162float(hp[2].y));
    lo.w = packbf2(v1.z - __bfloat162float(hp[3].x), v1.w - __bfloat162float(hp[3].y));
}

// SMEM byte offsets
#define OF_WA   0
#define OF_RED  1024
#define OF_AHI  4096       // 128x128 bf16 = 32768; reused as Z fp16 stage post-MMA
#define OF_ALO  36864      // reused as Zi fp16 stage post-MMA
#define OF_BHI  69632      // 256x128 bf16 = 65536
#define OF_BLO  135168
#define SMEM_SZ 200704

// ============ persistent split-bf16 mma.sync GEMM (R4 mainloop + staged epilogue) ============
__global__ __launch_bounds__(512, 1)
void gemm_mma(const float* __restrict__ A, const float* __restrict__ Ww,
              const float* __restrict__ Wu, const float* __restrict__ Wa,
              __half* __restrict__ Zh, __half* __restrict__ Zih,
              float* __restrict__ Ssrc, float* __restrict__ Sdst,
              int n, int ntiles)
{
    extern __shared__ char sm[];
    const uint32_t smb = smem_u32(sm);
    const int tid = threadIdx.x, warp = tid >> 5, lane = tid & 31;
    const int wr = warp >> 2, wc = warp & 3;
    const int r0 = wr * 32, n0 = wc * 64;

    if (tid < 256) ((float*)(sm + OF_WA))[tid] = Wa[tid];

    // ---- convert B once per CTA ----
    for (int i = tid; i < 4096; i += 512) {
        int r = i >> 4, ch = i & 15;
        const float* W = (r < 128) ? Ww : Wu;
        const float* g = W + (size_t)(r & 127) * HD + ch * 8;
        float4 v0 = *(const float4*)g, v1 = *(const float4*)(g + 4);
        uint4 hi, lo; split8(v0, v1, hi, lo);
        uint32_t off = (uint32_t)r * 256u + (uint32_t)(ch ^ (r & 7)) * 16u;
        *(uint4*)(sm + OF_BHI + off) = hi;
        *(uint4*)(sm + OF_BLO + off) = lo;
    }

    // ldmatrix lane mappings
    const int arow = (lane & 15);
    const int akb  = lane >> 4;
    const int brow = ((lane >> 4) << 3) + (lane & 7);
    const int bkb  = (lane >> 3) & 1;

    // per-thread A chunk mapping
    int crow[4], cch[4];
    #pragma unroll
    for (int i = 0; i < 4; i++) { int idx = tid + i * 512; crow[i] = idx >> 4; cch[i] = idx & 15; }

    // prefetch first tile's A
    float4 va[4][2];
    {
        int p0 = blockIdx.x * 128;
        #pragma unroll
        for (int i = 0; i < 4; i++) {
            bool p = (blockIdx.x < ntiles) && (p0 + crow[i] < n);
            const float* g = A + (size_t)(p0 + crow[i]) * HD + cch[i] * 8;
            va[i][0] = p ? *(const float4*)g       : make_float4(0.f,0.f,0.f,0.f);
            va[i][1] = p ? *(const float4*)(g + 4) : make_float4(0.f,0.f,0.f,0.f);
        }
    }
    __syncthreads();

    float* red = (float*)(sm + OF_RED);
    const float* WaS = (const float*)(sm + OF_WA);

    for (int tile = blockIdx.x; tile < ntiles; tile += gridDim.x) {
        const int row0 = tile * 128;
        const bool full = (row0 + 128 <= n);

        // ---- convert prefetched A -> smem hi/lo ----
        #pragma unroll
        for (int i = 0; i < 4; i++) {
            uint4 hi, lo; split8(va[i][0], va[i][1], hi, lo);
            uint32_t off = (uint32_t)crow[i] * 256u + (uint32_t)(cch[i] ^ (crow[i] & 7)) * 16u;
            *(uint4*)(sm + OF_AHI + off) = hi;
            *(uint4*)(sm + OF_ALO + off) = lo;
        }
        __syncthreads();

        // ---- MMA: 3 passes x 8 K-steps (R4 structure: let ptxas schedule) ----
        float c[2][8][4];
        #pragma unroll
        for (int mi = 0; mi < 2; mi++)
            #pragma unroll
            for (int nt = 0; nt < 8; nt++)
                #pragma unroll
                for (int q = 0; q < 4; q++) c[mi][nt][q] = 0.f;

        #pragma unroll 1
        for (int pass = 0; pass < 3; pass++) {
            const uint32_t abase = smb + ((pass == 2) ? OF_ALO : OF_AHI);
            const uint32_t bbase = smb + ((pass == 1) ? OF_BLO : OF_BHI);
            #pragma unroll
            for (int s = 0; s < 8; s++) {
                uint32_t a[2][4], b[4][4];
                #pragma unroll
                for (int mi = 0; mi < 2; mi++) {
                    int r = r0 + mi * 16 + arow;
                    ldsm4(a[mi], abase + (uint32_t)r * 256u
                                 + (uint32_t)((2 * s + akb) ^ (r & 7)) * 16u);
                }
                #pragma unroll
                for (int p = 0; p < 4; p++) {
                    int r = n0 + p * 16 + brow;
                    ldsm4(b[p], bbase + (uint32_t)r * 256u
                                 + (uint32_t)((2 * s + bkb) ^ (r & 7)) * 16u);
                }
                #pragma unroll
                for (int mi = 0; mi < 2; mi++)
                    #pragma unroll
                    for (int p = 0; p < 4; p++) {
                        mma16816(c[mi][2 * p],     a[mi], &b[p][0]);
                        mma16816(c[mi][2 * p + 1], a[mi], &b[p][2]);
                    }
            }
        }

        // ---- prefetch next tile's A (hidden under epilogue) ----
        {
            int pt = tile + gridDim.x;
            int p0 = pt * 128;
            #pragma unroll
            for (int i = 0; i < 4; i++) {
                bool p = (pt < ntiles) && (p0 + crow[i] < n);
                const float* g = A + (size_t)(p0 + crow[i]) * HD + cch[i] * 8;
                va[i][0] = p ? *(const float4*)g       : make_float4(0.f,0.f,0.f,0.f);
                va[i][1] = p ? *(const float4*)(g + 4) : make_float4(0.f,0.f,0.f,0.f);
            }
        }

        // ---- row-dots for s_src/s_dst (from fragments, Z columns only) ----
        if (wc < 2) {
            float ssv[2][2] = {{0.f,0.f},{0.f,0.f}}, sdv[2][2] = {{0.f,0.f},{0.f,0.f}};
            #pragma unroll
            for (int mi = 0; mi < 2; mi++)
                #pragma unroll
                for (int nt = 0; nt < 8; nt++) {
                    int col = n0 + nt * 8 + (lane & 3) * 2;
                    float s0 = WaS[col], s1 = WaS[col + 1];
                    float d0 = WaS[128 + col], d1 = WaS[128 + col + 1];
                    ssv[mi][0] += c[mi][nt][0] * s0 + c[mi][nt][1] * s1;
                    ssv[mi][1] += c[mi][nt][2] * s0 + c[mi][nt][3] * s1;
                    sdv[mi][0] += c[mi][nt][0] * d0 + c[mi][nt][1] * d1;
                    sdv[mi][1] += c[mi][nt][2] * d0 + c[mi][nt][3] * d1;
                }
            #pragma unroll
            for (int mi = 0; mi < 2; mi++)
                #pragma unroll
                for (int h = 0; h < 2; h++) {
                    ssv[mi][h] += __shfl_xor_sync(0xffffffffu, ssv[mi][h], 1);
                    ssv[mi][h] += __shfl_xor_sync(0xffffffffu, ssv[mi][h], 2);
                    sdv[mi][h] += __shfl_xor_sync(0xffffffffu, sdv[mi][h], 1);
                    sdv[mi][h] += __shfl_xor_sync(0xffffffffu, sdv[mi][h], 2);
                }
            if ((lane & 3) == 0) {
                int g = lane >> 2;
                #pragma unroll
                for (int mi = 0; mi < 2; mi++) {
                    int rl = r0 + mi * 16 + g;
                    red[rl * 2 + wc]             = ssv[mi][0];
                    red[(rl + 8) * 2 + wc]       = ssv[mi][1];
                    red[256 + rl * 2 + wc]       = sdv[mi][0];
                    red[256 + (rl + 8) * 2 + wc] = sdv[mi][1];
                }
            }
        }
        __syncthreads();   // all MMA reads of A-smem done -> safe to reuse as stage

        // ---- stage C -> SMEM as fp16 (Z @ OF_AHI, Zi @ OF_ALO), swizzled ----
        {
            char* zstg  = sm + OF_AHI;
            char* zistg = sm + OF_ALO;
            char* base  = (wc < 2) ? zstg : zistg;
            int   cn0   = (wc < 2) ? n0 : (n0 - 128);
            #pragma unroll
            for (int mi = 0; mi < 2; mi++)
                #pragma unroll
                for (int nt = 0; nt < 8; nt++) {
                    int chk = (cn0 >> 3) + nt;              // 16B chunk index (0..15)
                    int rA = r0 + mi * 16 + (lane >> 2), rB = rA + 8;
                    __half2 hA = __floats2half2_rn(c[mi][nt][0], c[mi][nt][1]);
                    __half2 hB = __floats2half2_rn(c[mi][nt][2], c[mi][nt][3]);
                    *(__half2*)(base + rA * 256 + ((chk ^ (rA & 7)) * 16) + (lane & 3) * 4) = hA;
                    *(__half2*)(base + rB * 256 + ((chk ^ (rB & 7)) * 16) + (lane & 3) * 4) = hB;
                }
        }
        __syncthreads();

        // ---- coalesced global stores: Z, Zi (16B chunks), Ssrc/Sdst ----
        #pragma unroll
        for (int k = 0; k < 4; k++) {
            int i = tid + k * 512;                          // 2048 chunks of Z
            int r = i >> 4, ch = i & 15;
            int grow = row0 + r;
            uint4 v = *(uint4*)(sm + OF_AHI + r * 256 + ((ch ^ (r & 7)) * 16));
            if (full || grow < n)
                *(uint4*)((char*)(Zh + (size_t)grow * HD) + ch * 16) = v;
        }
        #pragma unroll
        for (int k = 0; k < 4; k++) {
            int i = tid + k * 512;
            int r = i >> 4, ch = i & 15;
            int grow = row0 + r;
            uint4 v = *(uint4*)(sm + OF_ALO + r * 256 + ((ch ^ (r & 7)) * 16));
            if (full || grow < n)
                *(uint4*)((char*)(Zih + (size_t)grow * HD) + ch * 16) = v;
        }
        if (tid < 128) {
            int grow = row0 + tid;
            if (full || grow < n) {
                Ssrc[grow] = red[tid * 2] + red[tid * 2 + 1];
                Sdst[grow] = red[256 + tid * 2] + red[256 + tid * 2 + 1];
            }
        }
        __syncthreads();   // staging reads done -> safe for next tile's A convert
    }
}

// ================== edge / attention kernel (Z, Zi in fp16) =====================
__global__ __launch_bounds__(256)
void edge_kernel(const __half* __restrict__ Zh, const __half* __restrict__ Zih,
                 const float* __restrict__ Ssrc, const float* __restrict__ Sdst,
                 const float* __restrict__ edge_d, const int* __restrict__ esrc,
                 const float* __restrict__ W_V, const float* __restrict__ Wa,
                 float* __restrict__ out, int n)
{
    int gw = (blockIdx.x * blockDim.x + threadIdx.x) >> 5;
    if (gw >= n) return;
    const int lane = threadIdx.x & 31;
    const int node = gw;
    const float cva = W_V[0] * Wa[2 * HD];

    int   e   = node * 16 + (lane & 15);
    int   src = esrc[e];
    float ee  = Ssrc[src] + Sdst[node] + edge_d[e] * cva;
    ee = ee > 0.f ? ee : 0.01f * ee;

    float m = ee;
    #pragma unroll
    for (int off = 8; off; off >>= 1) m = fmaxf(m, __shfl_xor_sync(0xffffffffu, m, off));
    float ex = __expf(ee - m);
    float s = ex;
    #pragma unroll
    for (int off = 8; off; off >>= 1) s += __shfl_xor_sync(0xffffffffu, s, off);
    float alpha = ex / s;

    float4 acc = make_float4(0.f, 0.f, 0.f, 0.f);
    #pragma unroll
    for (int j = 0; j < 16; j++) {
        float aj = __shfl_sync(0xffffffffu, alpha, j);
        int   sj = __shfl_sync(0xffffffffu, src,   j);
        uint2 raw = *(const uint2*)(Zh + (size_t)sj * HD + lane * 4);
        float2 f0 = __half22float2(*(__half2*)&raw.x);
        float2 f1 = __half22float2(*(__half2*)&raw.y);
        acc.x += aj * f0.x; acc.y += aj * f0.y; acc.z += aj * f1.x; acc.w += aj * f1.y;
    }

    uint2 zr = *(const uint2*)(Zih + (size_t)node * HD + lane * 4);
    float2 z0 = __half22float2(*(__half2*)&zr.x);
    float2 z1 = __half22float2(*(__half2*)&zr.y);
    float4 o;
    o.x = fmaxf(z0.x + acc.x, 0.f);
    o.y = fmaxf(z0.y + acc.y, 0.f);
    o.z = fmaxf(z1.x + acc.z, 0.f);
    o.w = fmaxf(z1.y + acc.w, 0.f);
    *(float4*)(out + (size_t)node * HD + lane * 4) = o;
}

extern "C" void kernel_launch(void* const* d_in, const int* in_sizes, int n_in,
                              void* d_out, int out_size)
{
    const float* attr   = (const float*)d_in[0];
    const float* edge_d = (const float*)d_in[1];
    const float* W_V1   = (const float*)d_in[2];
    const float* W_W1   = (const float*)d_in[3];
    const float* W_U1   = (const float*)d_in[4];
    const float* W_a1   = (const float*)d_in[5];
    const float* W_V2   = (const float*)d_in[6];
    const float* W_W2   = (const float*)d_in[7];
    const float* W_U2   = (const float*)d_in[8];
    const float* W_a2   = (const float*)d_in[9];
    const int*   esrc   = (const int*)d_in[10];

    const int n = in_sizes[0] / HD;

    float *zp, *zip, *ssp, *sdp, *h1p;
    cudaGetSymbolAddress((void**)&zp,  g_z);
    cudaGetSymbolAddress((void**)&zip, g_zi);
    cudaGetSymbolAddress((void**)&ssp, g_ss);
    cudaGetSymbolAddress((void**)&sdp, g_sd);
    cudaGetSymbolAddress((void**)&h1p, g_h1);
    __half* zhp  = (__half*)zp;
    __half* zihp = (__half*)zip;

    cudaFuncSetAttribute(gemm_mma, cudaFuncAttributeMaxDynamicSharedMemorySize, SMEM_SZ);

    int nsm = 148;
    cudaDeviceGetAttribute(&nsm, cudaDevAttrMultiProcessorCount, 0);

    const int ntiles = (n + 127) / 128;
    const int gb = (nsm < ntiles) ? nsm : ntiles;
    const int eb = (n + 7) / 8;

    gemm_mma<<<gb, 512, SMEM_SZ>>>(attr, W_W1, W_U1, W_a1, zhp, zihp, ssp, sdp, n, ntiles);
    edge_kernel<<<eb, 256>>>(zhp, zihp, ssp, sdp, edge_d, esrc, W_V1, W_a1, h1p, n);
    gemm_mma<<<gb, 512, SMEM_SZ>>>(h1p, W_W2, W_U2, W_a2, zhp, zihp, ssp, sdp, n, ntiles);
    edge_kernel<<<eb, 256>>>(zhp, zihp, ssp, sdp, edge_d, esrc, W_V2, W_a2, (float*)d_out, n);
}